// round 15
// baseline (speedup 1.0000x reference)
#include <cuda_runtime.h>
#include <math.h>

// Problem constants (fixed by reference)
#define T_STEPS 128
#define MATPTS  16
#define PPT     2                    // material points per thread per chain
#define TPB     (MATPTS / PPT)       // threads per batch element = 8
#define BLOCK   128

// Material constants, derived in double precision at compile time
static constexpr double E_MOD_D = 3130.0;
static constexpr double NU_D    = 0.37;
static constexpr double MU_D    = E_MOD_D / (2.0 * (1.0 + NU_D));
static constexpr double LAM_D   = E_MOD_D * NU_D / ((1.0 + NU_D) * (1.0 - 2.0 * NU_D));
static constexpr double SIGY_D  = 64.8;
static constexpr double H_D     = 300.0;
static constexpr double KINV_D  = 1.0 / (3.0 * MU_D + H_D);
static constexpr double SQRT3_D = 1.7320508075688772;

static constexpr float TWO_MU_F = (float)(2.0 * MU_D);
static constexpr float K3_F     = (float)(LAM_D + 2.0 * MU_D / 3.0);  // pm = K3*(e0+e1)
static constexpr float NC23_F   = (float)(-2.0 * MU_D / 3.0);         // deviator correction
static constexpr float KS3_F    = (float)(SQRT3_D * KINV_D);          // Kinv*sqrt(3)
static constexpr float NHK_F    = (float)(-H_D * KINV_D);             // -H*Kinv
static constexpr float NYS0_F   = (float)(-SIGY_D * KINV_D);          // initial yield state
static constexpr float N15S3_F  = (float)(-1.5 / SQRT3_D);            // -1.5/sqrt(3)

// ---- packed fp32x2 helpers (sm_100+ only) ---------------------------------
typedef unsigned long long u64t;
struct F2 { u64t v; };

__device__ __forceinline__ F2 f2pack(float lo, float hi) {
    F2 r; asm("mov.b64 %0, {%1, %2};" : "=l"(r.v) : "f"(lo), "f"(hi)); return r;
}
__device__ __forceinline__ void f2unpack(F2 a, float& lo, float& hi) {
    asm("mov.b64 {%0, %1}, %2;" : "=f"(lo), "=f"(hi) : "l"(a.v));
}
__device__ __forceinline__ F2 f2fma(F2 a, F2 b, F2 c) {
    F2 r; asm("fma.rn.f32x2 %0, %1, %2, %3;" : "=l"(r.v) : "l"(a.v), "l"(b.v), "l"(c.v)); return r;
}
__device__ __forceinline__ F2 f2add(F2 a, F2 b) {
    F2 r; asm("add.rn.f32x2 %0, %1, %2;" : "=l"(r.v) : "l"(a.v), "l"(b.v)); return r;
}
__device__ __forceinline__ F2 f2mul(F2 a, F2 b) {
    F2 r; asm("mul.rn.f32x2 %0, %1, %2;" : "=l"(r.v) : "l"(a.v), "l"(b.v)); return r;
}
__device__ __forceinline__ F2 f2relu(F2 a) {
    float lo, hi; f2unpack(a, lo, hi);
    return f2pack(fmaxf(lo, 0.0f), fmaxf(hi, 0.0f));
}
__device__ __forceinline__ F2 f2zero() { F2 r; r.v = 0ULL; return r; }

__global__ void __launch_bounds__(BLOCK, 4)
prnn_j2_kernel(const float* __restrict__ x,
               const float* __restrict__ W1,
               const float* __restrict__ W2,
               float* __restrict__ out,
               int B)
{
    const int tid = blockIdx.x * BLOCK + threadIdx.x;
    const int Bh  = (B + 1) >> 1;        // chains per thread cover batches g and g+Bh
    const int grp = tid >> 3;            // batch group (first chain's batch)
    const int sub = tid & 7;             // sub-lane within the 8-thread group
    if (grp >= Bh) return;

    const int b0 = grp;
    const int b1 = grp + Bh;
    const bool ch1_valid = (b1 < B);
    const int b1c = ch1_valid ? b1 : b0;  // clamp (loads safe; stores predicated)

    // loop-invariant predicates / routing for the transpose-reduction
    const bool lo4 = (sub < 4);
    const bool lo2 = (sub < 2);
    const bool mid = (sub < 4) && (sub >= 2);
    const bool r2sel = ((sub & 2) != 0);
    const bool st0 = ((sub & 1) == 0) && (sub < 6);
    const bool st1 = st0 && ch1_valid;
    const int  comp = sub >> 1;

    // ---- Packed per-thread weight slices (SHARED by both chains) --------
    // W1 row 2 (shear) pre-scaled by 0.5 so eexy = e2' + npxy.
    const int mlo = sub * PPT;
    F2 w1p[3][3];
    F2 w2p[3][3];
    #pragma unroll
    for (int j = 0; j < 3; ++j) {
        const float sc = (j == 2) ? 0.5f : 1.0f;
        #pragma unroll
        for (int f = 0; f < 3; ++f)
            w1p[j][f] = f2pack(sc * __ldg(&W1[(3 * mlo + j) * 3 + f]),
                               sc * __ldg(&W1[(3 * (mlo + 1) + j) * 3 + f]));
    }
    #pragma unroll
    for (int o = 0; o < 3; ++o)
        #pragma unroll
        for (int j = 0; j < 3; ++j) {
            float wl = __ldg(&W2[o * 48 + 3 * mlo + j]);
            float wh = __ldg(&W2[o * 48 + 3 * (mlo + 1) + j]);
            w2p[o][j] = f2pack(log1pf(expf(wl)), log1pf(expf(wh)));
        }

    // ---- Packed constants --------------------------------------------------
    const F2 TWOMU2 = f2pack(TWO_MU_F, TWO_MU_F);
    const F2 K32    = f2pack(K3_F,     K3_F);
    const F2 NC232  = f2pack(NC23_F,   NC23_F);
    const F2 KS32   = f2pack(KS3_F,    KS3_F);
    const F2 NHK2   = f2pack(NHK_F,    NHK_F);
    const F2 N15S32 = f2pack(N15S3_F,  N15S3_F);
    const F2 ONE2   = f2pack(1.0f,     1.0f);
    const F2 TINY2  = f2pack(1e-24f,   1e-24f);

    // ---- Committed history: TWO independent chains -----------------------
    F2 npxx[2], npyy[2], npxy[2], nysK[2];
    #pragma unroll
    for (int c = 0; c < 2; ++c) {
        npxx[c] = f2zero(); npyy[c] = f2zero(); npxy[c] = f2zero();
        nysK[c] = f2pack(NYS0_F, NYS0_F);
    }

    const float2* xq0 = (const float2*)(x + (size_t)b0  * (T_STEPS * 3));
    const float2* xq1 = (const float2*)(x + (size_t)b1c * (T_STEPS * 3));
    float* op0 = out + (size_t)b0 * (T_STEPS * 3) + comp;
    float* op1 = out + (size_t)b1 * (T_STEPS * 3) + comp;   // only used if st1

    // J2 update + fc2 partials for chain c (state indexed by c)
    auto math = [&](int c, float ex, float ey, float eg,
                    float& r0, float& r1, float& r2) {
        const F2 ex2 = f2pack(ex, ex);
        const F2 ey2 = f2pack(ey, ey);
        const F2 eg2 = f2pack(eg, eg);

        const F2 e0 = f2fma(ex2, w1p[0][0], f2fma(ey2, w1p[0][1], f2mul(eg2, w1p[0][2])));
        const F2 e1 = f2fma(ex2, w1p[1][0], f2fma(ey2, w1p[1][1], f2mul(eg2, w1p[1][2])));
        const F2 e2 = f2fma(ex2, w1p[2][0], f2fma(ey2, w1p[2][1], f2mul(eg2, w1p[2][2])));

        const F2 eexx = f2add(e0, npxx[c]);
        const F2 eeyy = f2add(e1, npyy[c]);
        const F2 eexy = f2add(e2, npxy[c]);
        const F2 t01  = f2add(e0, e1);
        const F2 pm   = f2mul(K32,  t01);
        const F2 nctr = f2mul(NC232, t01);
        const F2 dxx  = f2fma(TWOMU2, eexx, nctr);
        const F2 dyy  = f2fma(TWOMU2, eeyy, nctr);
        const F2 sxy  = f2mul(TWOMU2, eexy);

        const F2 sd  = f2add(dxx, dyy);
        const F2 A   = f2fma(sxy, sxy, TINY2);
        const F2 p1  = f2mul(dxx, sd);
        const F2 p2  = f2fma(dyy, dyy, A);
        const F2 u2  = f2add(p1, p2);

        float u_lo, u_hi;
        f2unpack(u2, u_lo, u_hi);
        const F2 r2p = f2pack(rsqrtf(u_lo), rsqrtf(u_hi));
        const F2 nr2 = f2mul(N15S32, r2p);
        const F2 ur2 = f2mul(u2, r2p);              // sqrt(u) = q/sqrt(3)
        const F2 fk2 = f2fma(KS32, ur2, nysK[c]);   // Kinv*(q - sigy - H*alpha)
        const F2 dg2 = f2relu(fk2);
        nysK[c] = f2fma(NHK2, dg2, nysK[c]);
        const F2 nc2 = f2mul(dg2, nr2);             // -1.5*dgam/q

        npxx[c] = f2fma(nc2, dxx, npxx[c]);
        npyy[c] = f2fma(nc2, dyy, npyy[c]);
        npxy[c] = f2fma(nc2, sxy, npxy[c]);

        const F2 wf  = f2fma(TWOMU2, nc2, ONE2);
        const F2 oxx = f2fma(dxx, wf, pm);
        const F2 oyy = f2fma(dyy, wf, pm);
        const F2 oxy = f2mul(sxy, wf);

        const F2 a0 = f2fma(oxx, w2p[0][0], f2fma(oyy, w2p[0][1], f2mul(oxy, w2p[0][2])));
        const F2 a1 = f2fma(oxx, w2p[1][0], f2fma(oyy, w2p[1][1], f2mul(oxy, w2p[1][2])));
        const F2 a2 = f2fma(oxx, w2p[2][0], f2fma(oyy, w2p[2][1], f2mul(oxy, w2p[2][2])));

        float a0l, a0h, a1l, a1h, a2l, a2h;
        f2unpack(a0, a0l, a0h);
        f2unpack(a1, a1l, a1h);
        f2unpack(a2, a2l, a2h);
        r0 = a0l + a0h; r1 = a1l + a1h; r2 = a2l + a2h;
    };

    // transpose-reduction over the 8-lane group (4 SHFL) + predicated store
    auto reduce_store = [&](float r0, float r1, float r2, float* dst, bool en) {
        float v1 = lo4 ? r2 : r0;
        float w1 = __shfl_xor_sync(0xffffffffu, v1, 4);
        if (lo4) r0 += w1; else r2 += w1;
        float w2 = __shfl_xor_sync(0xffffffffu, r1, 4);
        if (lo4) r1 += w2;
        float v3 = lo4 ? (r2sel ? r0 : r1) : r2;
        float w3 = __shfl_xor_sync(0xffffffffu, v3, 2);
        if (lo2)      r0 += w3;
        else if (mid) r1 += w3;
        else          r2 += w3;
        float v4 = lo2 ? r0 : (lo4 ? r1 : r2);
        float w4 = __shfl_xor_sync(0xffffffffu, v4, 1);
        const float total = v4 + w4;
        if (en) *dst = total;
    };

    #pragma unroll 1
    for (int k = 0; k < T_STEPS / 2; ++k) {
        // per-iteration x loads for both chains (L1/L2 resident; latency
        // covered by the other chain's math)
        const float2 aA = xq0[0], aB = xq0[1], aC = xq0[2];
        const float2 bA = xq1[0], bB = xq1[1], bC = xq1[2];

        float x0, x1, x2, y0, y1, y2;

        // step 2k: both chains' math back-to-back (independent -> ILP),
        // then both reductions (independent SHFL chains pipeline).
        math(0, aA.x, aA.y, aB.x, x0, x1, x2);
        math(1, bA.x, bA.y, bB.x, y0, y1, y2);
        reduce_store(x0, x1, x2, op0 + 6 * k,     st0);
        reduce_store(y0, y1, y2, op1 + 6 * k,     st1);

        // step 2k+1
        math(0, aB.y, aC.x, aC.y, x0, x1, x2);
        math(1, bB.y, bC.x, bC.y, y0, y1, y2);
        reduce_store(x0, x1, x2, op0 + 6 * k + 3, st0);
        reduce_store(y0, y1, y2, op1 + 6 * k + 3, st1);

        xq0 += 3;
        xq1 += 3;
    }
}

extern "C" void kernel_launch(void* const* d_in, const int* in_sizes, int n_in,
                              void* d_out, int out_size)
{
    const float* x  = (const float*)d_in[0];   // [B, T, 3]
    const float* W1 = (const float*)d_in[1];   // [48, 3]
    const float* W2 = (const float*)d_in[2];   // [3, 48]
    float* out      = (float*)d_out;           // [B, T, 3]

    const int B  = in_sizes[0] / (T_STEPS * 3);
    const int Bh = (B + 1) / 2;                // batch groups (2 chains/thread)
    const int total_threads = Bh * TPB;
    const int grid = (total_threads + BLOCK - 1) / BLOCK;

    prnn_j2_kernel<<<grid, BLOCK>>>(x, W1, W2, out, B);
}

// round 16
// speedup vs baseline: 1.0527x; 1.0527x over previous
#include <cuda_runtime.h>
#include <math.h>

// Problem constants (fixed by reference)
#define T_STEPS 128
#define MATPTS  16
#define PPT     4                    // material points per thread (2 packed pairs)
#define TPB     (MATPTS / PPT)       // threads per batch element = 4
#define BLOCK   128

// Material constants, derived in double precision at compile time
static constexpr double E_MOD_D = 3130.0;
static constexpr double NU_D    = 0.37;
static constexpr double MU_D    = E_MOD_D / (2.0 * (1.0 + NU_D));
static constexpr double LAM_D   = E_MOD_D * NU_D / ((1.0 + NU_D) * (1.0 - 2.0 * NU_D));
static constexpr double SIGY_D  = 64.8;
static constexpr double H_D     = 300.0;
static constexpr double KINV_D  = 1.0 / (3.0 * MU_D + H_D);
static constexpr double SQRT3_D = 1.7320508075688772;

static constexpr float TWO_MU_F = (float)(2.0 * MU_D);
static constexpr float K3_F     = (float)(LAM_D + 2.0 * MU_D / 3.0);  // pm = K3*(e0+e1)
static constexpr float NC23_F   = (float)(-2.0 * MU_D / 3.0);         // deviator correction
static constexpr float KS3_F    = (float)(SQRT3_D * KINV_D);          // Kinv*sqrt(3)
static constexpr float NHK_F    = (float)(-H_D * KINV_D);             // -H*Kinv
static constexpr float NYS0_F   = (float)(-SIGY_D * KINV_D);          // initial yield state
static constexpr float N15S3_F  = (float)(-1.5 / SQRT3_D);            // -1.5/sqrt(3)

// ---- packed fp32x2 helpers (sm_100+ only) ---------------------------------
typedef unsigned long long u64t;
struct F2 { u64t v; };

__device__ __forceinline__ F2 f2pack(float lo, float hi) {
    F2 r; asm("mov.b64 %0, {%1, %2};" : "=l"(r.v) : "f"(lo), "f"(hi)); return r;
}
__device__ __forceinline__ void f2unpack(F2 a, float& lo, float& hi) {
    asm("mov.b64 {%0, %1}, %2;" : "=f"(lo), "=f"(hi) : "l"(a.v));
}
__device__ __forceinline__ F2 f2fma(F2 a, F2 b, F2 c) {
    F2 r; asm("fma.rn.f32x2 %0, %1, %2, %3;" : "=l"(r.v) : "l"(a.v), "l"(b.v), "l"(c.v)); return r;
}
__device__ __forceinline__ F2 f2add(F2 a, F2 b) {
    F2 r; asm("add.rn.f32x2 %0, %1, %2;" : "=l"(r.v) : "l"(a.v), "l"(b.v)); return r;
}
__device__ __forceinline__ F2 f2mul(F2 a, F2 b) {
    F2 r; asm("mul.rn.f32x2 %0, %1, %2;" : "=l"(r.v) : "l"(a.v), "l"(b.v)); return r;
}
__device__ __forceinline__ F2 f2relu(F2 a) {
    float lo, hi; f2unpack(a, lo, hi);
    return f2pack(fmaxf(lo, 0.0f), fmaxf(hi, 0.0f));
}
__device__ __forceinline__ F2 f2zero() { F2 r; r.v = 0ULL; return r; }

__global__ void __launch_bounds__(BLOCK, 4)
prnn_j2_kernel(const float* __restrict__ x,
               const float* __restrict__ W1,
               const float* __restrict__ W2,
               float* __restrict__ out,
               int B)
{
    const int tid = blockIdx.x * BLOCK + threadIdx.x;
    const int b   = tid >> 2;           // batch element
    const int sub = tid & 3;            // sub-lane within the 4-thread group
    if (b >= B) return;

    // routing predicates for the 3-SHFL transpose-reduction
    const bool lo2 = (sub < 2);          // lanes 0,1
    const bool s0  = (sub == 0);
    const bool s1  = (sub == 1);
    const bool do_store = (sub < 3);     // lane sub stores component sub

    // ---- Packed per-thread weight slices: 2 pairs -------------------------
    // Thread handles points m = 4*sub + {0..3}; pair p packs (4*sub+2p, +2p+1).
    // W1 row 2 (shear) pre-scaled by 0.5.
    F2 w1p[2][3][3];
    F2 w2p[2][3][3];
    #pragma unroll
    for (int p = 0; p < 2; ++p) {
        const int mlo = sub * PPT + 2 * p;
        #pragma unroll
        for (int j = 0; j < 3; ++j) {
            const float sc = (j == 2) ? 0.5f : 1.0f;
            #pragma unroll
            for (int f = 0; f < 3; ++f)
                w1p[p][j][f] = f2pack(sc * __ldg(&W1[(3 * mlo + j) * 3 + f]),
                                      sc * __ldg(&W1[(3 * (mlo + 1) + j) * 3 + f]));
        }
        #pragma unroll
        for (int o = 0; o < 3; ++o)
            #pragma unroll
            for (int j = 0; j < 3; ++j) {
                float wl = __ldg(&W2[o * 48 + 3 * mlo + j]);
                float wh = __ldg(&W2[o * 48 + 3 * (mlo + 1) + j]);
                w2p[p][o][j] = f2pack(log1pf(expf(wl)), log1pf(expf(wh)));
            }
    }

    // ---- Packed constants --------------------------------------------------
    const F2 TWOMU2 = f2pack(TWO_MU_F, TWO_MU_F);
    const F2 K32    = f2pack(K3_F,     K3_F);
    const F2 NC232  = f2pack(NC23_F,   NC23_F);
    const F2 KS32   = f2pack(KS3_F,    KS3_F);
    const F2 NHK2   = f2pack(NHK_F,    NHK_F);
    const F2 N15S32 = f2pack(N15S3_F,  N15S3_F);
    const F2 ONE2   = f2pack(1.0f,     1.0f);
    const F2 TINY2  = f2pack(1e-24f,   1e-24f);

    // ---- Committed history: 2 independent packed pairs --------------------
    F2 npxx[2], npyy[2], npxy[2], nysK[2];
    #pragma unroll
    for (int p = 0; p < 2; ++p) {
        npxx[p] = f2zero(); npyy[p] = f2zero(); npxy[p] = f2zero();
        nysK[p] = f2pack(NYS0_F, NYS0_F);
    }

    const float2* xq = (const float2*)(x + (size_t)b * (T_STEPS * 3));
    float*        opc = out + (size_t)b * (T_STEPS * 3) + sub;   // comp = sub

    // J2 update + fc2 partials for pair p, accumulated into r0,r1,r2
    auto math = [&](int p, F2 ex2, F2 ey2, F2 eg2,
                    float& r0, float& r1, float& r2) {
        // fc1: per-point strain (row 2 pre-scaled by 0.5)
        const F2 e0 = f2fma(ex2, w1p[p][0][0], f2fma(ey2, w1p[p][0][1], f2mul(eg2, w1p[p][0][2])));
        const F2 e1 = f2fma(ex2, w1p[p][1][0], f2fma(ey2, w1p[p][1][1], f2mul(eg2, w1p[p][1][2])));
        const F2 e2 = f2fma(ex2, w1p[p][2][0], f2fma(ey2, w1p[p][2][1], f2mul(eg2, w1p[p][2][2])));

        // elastic predictor, deviatoric form (state negated)
        const F2 eexx = f2add(e0, npxx[p]);
        const F2 eeyy = f2add(e1, npyy[p]);
        const F2 eexy = f2add(e2, npxy[p]);
        const F2 t01  = f2add(e0, e1);
        const F2 pm   = f2mul(K32,  t01);
        const F2 nctr = f2mul(NC232, t01);
        const F2 dxx  = f2fma(TWOMU2, eexx, nctr);
        const F2 dyy  = f2fma(TWOMU2, eeyy, nctr);
        const F2 sxy  = f2mul(TWOMU2, eexy);

        // u = dxx^2 + dxx*dyy + dyy^2 + sxy^2 (q^2 = 3u); TINY seed guards u=0
        const F2 sd  = f2add(dxx, dyy);
        const F2 A   = f2fma(sxy, sxy, TINY2);
        const F2 p1  = f2mul(dxx, sd);
        const F2 p2  = f2fma(dyy, dyy, A);
        const F2 u2  = f2add(p1, p2);

        // radial return (sqrt(3), Kinv folded); only rsqrt is scalar
        float u_lo, u_hi;
        f2unpack(u2, u_lo, u_hi);
        const F2 r2p = f2pack(rsqrtf(u_lo), rsqrtf(u_hi));
        const F2 nr2 = f2mul(N15S32, r2p);
        const F2 ur2 = f2mul(u2, r2p);               // sqrt(u) = q/sqrt(3)
        const F2 fk2 = f2fma(KS32, ur2, nysK[p]);    // Kinv*(q - sigy - H*alpha)
        const F2 dg2 = f2relu(fk2);
        nysK[p] = f2fma(NHK2, dg2, nysK[p]);
        const F2 nc2 = f2mul(dg2, nr2);              // -1.5*dgam/q

        // commit plastic strain
        npxx[p] = f2fma(nc2, dxx, npxx[p]);
        npyy[p] = f2fma(nc2, dyy, npyy[p]);
        npxy[p] = f2fma(nc2, sxy, npxy[p]);

        // corrected stress: o = d*(1 + 2mu*nc) + pm
        const F2 wf  = f2fma(TWOMU2, nc2, ONE2);
        const F2 oxx = f2fma(dxx, wf, pm);
        const F2 oyy = f2fma(dyy, wf, pm);
        const F2 oxy = f2mul(sxy, wf);

        // fc2 partial (softplus weights)
        const F2 a0 = f2fma(oxx, w2p[p][0][0], f2fma(oyy, w2p[p][0][1], f2mul(oxy, w2p[p][0][2])));
        const F2 a1 = f2fma(oxx, w2p[p][1][0], f2fma(oyy, w2p[p][1][1], f2mul(oxy, w2p[p][1][2])));
        const F2 a2 = f2fma(oxx, w2p[p][2][0], f2fma(oyy, w2p[p][2][1], f2mul(oxy, w2p[p][2][2])));

        float a0l, a0h, a1l, a1h, a2l, a2h;
        f2unpack(a0, a0l, a0h);
        f2unpack(a1, a1l, a1h);
        f2unpack(a2, a2l, a2h);
        r0 += a0l + a0h; r1 += a1l + a1h; r2 += a2l + a2h;
    };

    // one full step: both pairs' math (independent -> ILP) + 3-SHFL reduction
    auto step = [&](float ex, float ey, float eg, float* dst) {
        const F2 ex2 = f2pack(ex, ex);
        const F2 ey2 = f2pack(ey, ey);
        const F2 eg2 = f2pack(eg, eg);

        float r0 = 0.f, r1 = 0.f, r2 = 0.f;
        math(0, ex2, ey2, eg2, r0, r1, r2);
        math(1, ex2, ey2, eg2, r0, r1, r2);

        // ---- transpose-reduction over the 4-lane group: 3 SHFL total ----
        // A (mask 2): lanes{0,1} send r2, lanes{2,3} send r0
        float vA = lo2 ? r2 : r0;
        float wA = __shfl_xor_sync(0xffffffffu, vA, 2);
        if (lo2) r0 += wA; else r2 += wA;
        // B (mask 2): all send r1 -> every lane has r1 over its mask-1 pair cols
        float wB = __shfl_xor_sync(0xffffffffu, r1, 2);
        r1 += wB;
        // C (mask 1): lane0 sends r1, lane1 sends r0, lanes 2,3 send r2
        float vC = s0 ? r1 : (s1 ? r0 : r2);
        float wC = __shfl_xor_sync(0xffffffffu, vC, 1);
        float keep = s0 ? r0 : (s1 ? r1 : r2);
        const float total = keep + wC;

        if (do_store) *dst = total;
    };

    // software-pipelined pair loads (3 x LDG.64 per 2 steps)
    float2 cA = xq[0], cB = xq[1], cC = xq[2];

    #pragma unroll 1
    for (int k = 0; k < T_STEPS / 2; ++k) {
        // clamped prefetch of the next pair (no branch)
        const float2* nq = xq + ((k + 1 < T_STEPS / 2) ? 3 : 0);
        const float2 nA = nq[0], nB = nq[1], nC = nq[2];

        step(cA.x, cA.y, cB.x, opc);
        step(cB.y, cC.x, cC.y, opc + 3);

        cA = nA; cB = nB; cC = nC;
        xq += 3;
        opc += 6;
    }
}

extern "C" void kernel_launch(void* const* d_in, const int* in_sizes, int n_in,
                              void* d_out, int out_size)
{
    const float* x  = (const float*)d_in[0];   // [B, T, 3]
    const float* W1 = (const float*)d_in[1];   // [48, 3]
    const float* W2 = (const float*)d_in[2];   // [3, 48]
    float* out      = (float*)d_out;           // [B, T, 3]

    const int B = in_sizes[0] / (T_STEPS * 3);
    const int total_threads = B * TPB;
    const int grid = (total_threads + BLOCK - 1) / BLOCK;

    prnn_j2_kernel<<<grid, BLOCK>>>(x, W1, W2, out, B);
}